// round 14
// baseline (speedup 1.0000x reference)
#include <cuda_runtime.h>
#include <cstdint>

#define NMAX 200000
#define H_DIM 184
#define L1_DIM 188
#define GV_DIM (H_DIM + 16)   // 200 = k-dim of W1
#define H1_BLOCKS 10
#define H1_ROWS 20            // 10*20 = 200 = GV_DIM

// Per-node accumulator: agg (4f) + deg + pad => one 32B sector, both REDs of
// an edge hit a single L2 line.
struct __align__(32) NodeAcc {
    float4 agg;
    float  deg;
    float  pad0, pad1, pad2;
};

__device__ NodeAcc      g_nd[NMAX];
__device__ float4       g_x4[NMAX];       // packed node_feat[:, :4]
__device__ unsigned int g_x1[H_DIM];      // column max of h (uint bits; h>=0)
__device__ float        g_x2[H_DIM];      // h[center]
__device__ float        g_md[16];         // md MLP output (nf-only dependency)
// REPLAY INVARIANT: g_g1 == 0 at launch entry.  First call: BSS zero.
// Every call: head2 resets it after its final read (stream-serialized).
__device__ float        g_g1[L1_DIM];

__device__ __forceinline__ float rcp_fast(float x) {
    float r;
    asm("rcp.approx.f32 %0, %1;" : "=f"(r) : "f"(x));
    return r;
}
// ---- programmatic dependent launch (sm_90+) --------------------------------
__device__ __forceinline__ void pdl_launch_dependents() {
    asm volatile("griddepcontrol.launch_dependents;");
}
__device__ __forceinline__ void pdl_wait() {
    asm volatile("griddepcontrol.wait;" ::: "memory");
}

// ---------------------------------------------------------------------------
// Kernel 0: ONE pass per node: zero g_nd[i] (2 float4) + pack node_feat[:,:4]
// into g_x4[i].  md MLP on block 0 warp 0.  x1 zeroed by first H_DIM threads.
// ---------------------------------------------------------------------------
__global__ void __launch_bounds__(256) prep_kernel(
        const float* __restrict__ nf, int n_nodes,
        const int*   __restrict__ center,
        const float* __restrict__ W2,  const float* __restrict__ b2,
        const float* __restrict__ W21, const float* __restrict__ b21) {
    int stride = gridDim.x * blockDim.x;
    int tid = blockIdx.x * blockDim.x + threadIdx.x;

    pdl_launch_dependents();           // edge may start its stream loads

    // md = relu(relu(nf[c,4:6]@W2+b2)@W21+b21)  (block 0, warp 0)
    if (blockIdx.x == 0 && threadIdx.x < 32) {
        int t = threadIdx.x;
        int c = *center;
        float m0 = nf[(size_t)c * 6 + 4];
        float m1 = nf[(size_t)c * 6 + 5];
        float md1 = 0.0f;
        if (t < 16)
            md1 = fmaxf(fmaf(m0, W2[t], fmaf(m1, W2[16 + t], b2[t])), 0.0f);
        float s = (t < 16) ? b21[t] : 0.0f;
        #pragma unroll
        for (int k = 0; k < 16; k++) {
            float v = __shfl_sync(0xffffffff, md1, k);
            if (t < 16) s = fmaf(v, W21[k * 16 + t], s);
        }
        if (t < 16) g_md[t] = fmaxf(s, 0.0f);
    }

    if (tid < H_DIM) g_x1[tid] = 0u;

    const float4 z = make_float4(0.f, 0.f, 0.f, 0.f);
    for (int i = tid; i < n_nodes; i += stride) {
        const float2* p = reinterpret_cast<const float2*>(nf + (size_t)i * 6);
        float2 a = __ldg(p);
        float2 b = __ldg(p + 1);
        g_x4[i] = make_float4(a.x, a.y, b.x, b.y);
        float4* nd = reinterpret_cast<float4*>(&g_nd[i]);
        nd[0] = z;
        nd[1] = z;
    }
}

// ---------------------------------------------------------------------------
// Kernel 1: edge scatter.  Stream loads issued BEFORE pdl_wait (independent
// of prep); gathers + REDs after.  One LDG.128 gather + red.v4 + red.f32,
// both REDs in the same 32B sector of g_nd[d].  (At the LSU issue floor.)
// ---------------------------------------------------------------------------
__device__ __forceinline__ void do_edge(int s, int d, float w) {
    float4 x = __ldg(&g_x4[s]);
    float* ap = reinterpret_cast<float*>(&g_nd[d]);
    asm volatile("red.global.add.v4.f32 [%0], {%1, %2, %3, %4};"
                 :: "l"(ap), "f"(x.x * w), "f"(x.y * w),
                    "f"(x.z * w), "f"(x.w * w)
                 : "memory");
    asm volatile("red.global.add.f32 [%0], %1;"
                 :: "l"(ap + 4), "f"(1.0f) : "memory");
}

__global__ void __launch_bounds__(256) edge_kernel(const int*   __restrict__ ei,
                                                   const float* __restrict__ ew, int E) {
    int i    = blockIdx.x * blockDim.x + threadIdx.x;
    int nvec = E >> 2;
    int4 s, d;
    float4 w;
    bool active = (i < nvec);
    if (active) {                      // input streams: independent of prep
        s = __ldcs(reinterpret_cast<const int4*>(ei) + i);
        d = __ldcs(reinterpret_cast<const int4*>(ei + E) + i);
        w = __ldcs(reinterpret_cast<const float4*>(ew) + i);
    }
    pdl_launch_dependents();           // node may start its weight loads
    pdl_wait();                        // prep's g_x4 / g_nd now visible

    if (active) {
        do_edge(s.x, d.x, w.x);
        do_edge(s.y, d.y, w.y);
        do_edge(s.z, d.z, w.z);
        do_edge(s.w, d.w, w.w);
    }
    if (i == 0) {                      // tail (E % 4)
        for (int e = nvec * 4; e < E; e++)
            do_edge(ei[e], ei[E + e], ew[e]);
    }
}

// ---------------------------------------------------------------------------
// Kernel 2: h = relu(mean@W_rel + b_rel + x@W_root); 4 nodes per iteration
// (quarter-strided).  Weights + W1/W4 prefetch loaded BEFORE pdl_wait.
// Per-block running max, one atomicMax per column per block.
// ---------------------------------------------------------------------------
__global__ void __launch_bounds__(192) node_kernel(
        const float* __restrict__ Wrel,
        const float* __restrict__ brel,
        const float* __restrict__ Wroot,
        int N, const int* __restrict__ center,
        const float* __restrict__ W1, const float* __restrict__ W4) {
    // L2 prefetch of head weights (2 lines per block, fire-and-forget)
    {
        const int W1_LINES = (GV_DIM * L1_DIM * 4 + 127) / 128;   // 1175
        int l = blockIdx.x + (int)gridDim.x * (threadIdx.x & 1);
        if (threadIdx.x < 2 && l < W1_LINES) {
            const char* p = reinterpret_cast<const char*>(W1) + (size_t)l * 128;
            asm volatile("prefetch.global.L2 [%0];" :: "l"(p));
        }
        if (blockIdx.x == 0 && threadIdx.x >= 64 && threadIdx.x < 94) {
            const char* p = reinterpret_cast<const char*>(W4)
                          + (size_t)(threadIdx.x - 64) * 128;
            asm volatile("prefetch.global.L2 [%0];" :: "l"(p));
        }
    }

    int j = threadIdx.x;
    if (j >= H_DIM) return;

    // weight loads: independent of edge output
    float wr0 = Wrel[j],             wr1 = Wrel[H_DIM + j];
    float wr2 = Wrel[2 * H_DIM + j], wr3 = Wrel[3 * H_DIM + j];
    float wo0 = Wroot[j],            wo1 = Wroot[H_DIM + j];
    float wo2 = Wroot[2 * H_DIM + j], wo3 = Wroot[3 * H_DIM + j];
    float bj  = brel[j];
    int   c   = *center;

    pdl_launch_dependents();           // head1 may start preloading W1
    pdl_wait();                        // edge's g_nd now complete

    int Q = (N + 3) >> 2;
    float m = 0.0f;                              // h >= 0 after ReLU

    for (int n0 = blockIdx.x; n0 < Q; n0 += gridDim.x) {
        int n1 = n0 + Q, n2 = n0 + 2 * Q, n3 = n0 + 3 * Q;
        bool v1 = (n1 < N), v2 = (n2 < N), v3 = (n3 < N);
        int c1 = v1 ? n1 : n0, c2 = v2 ? n2 : n0, c3 = v3 ? n3 : n0;

        float4 agA = g_nd[n0].agg;  float dgA = g_nd[n0].deg;  float4 xA = g_x4[n0];
        float4 agB = g_nd[c1].agg;  float dgB = g_nd[c1].deg;  float4 xB = g_x4[c1];
        float4 agC = g_nd[c2].agg;  float dgC = g_nd[c2].deg;  float4 xC = g_x4[c2];
        float4 agD = g_nd[c3].agg;  float dgD = g_nd[c3].deg;  float4 xD = g_x4[c3];

        float iA = rcp_fast(fmaxf(dgA, 1.0f));
        float iB = rcp_fast(fmaxf(dgB, 1.0f));
        float iC = rcp_fast(fmaxf(dgC, 1.0f));
        float iD = rcp_fast(fmaxf(dgD, 1.0f));

        float hA = bj, hB = bj, hC = bj, hD = bj;
        hA = fmaf(agA.x * iA, wr0, hA);  hB = fmaf(agB.x * iB, wr0, hB);
        hC = fmaf(agC.x * iC, wr0, hC);  hD = fmaf(agD.x * iD, wr0, hD);
        hA = fmaf(agA.y * iA, wr1, hA);  hB = fmaf(agB.y * iB, wr1, hB);
        hC = fmaf(agC.y * iC, wr1, hC);  hD = fmaf(agD.y * iD, wr1, hD);
        hA = fmaf(agA.z * iA, wr2, hA);  hB = fmaf(agB.z * iB, wr2, hB);
        hC = fmaf(agC.z * iC, wr2, hC);  hD = fmaf(agD.z * iD, wr2, hD);
        hA = fmaf(agA.w * iA, wr3, hA);  hB = fmaf(agB.w * iB, wr3, hB);
        hC = fmaf(agC.w * iC, wr3, hC);  hD = fmaf(agD.w * iD, wr3, hD);
        hA = fmaf(xA.x, wo0, hA);  hB = fmaf(xB.x, wo0, hB);
        hC = fmaf(xC.x, wo0, hC);  hD = fmaf(xD.x, wo0, hD);
        hA = fmaf(xA.y, wo1, hA);  hB = fmaf(xB.y, wo1, hB);
        hC = fmaf(xC.y, wo1, hC);  hD = fmaf(xD.y, wo1, hD);
        hA = fmaf(xA.z, wo2, hA);  hB = fmaf(xB.z, wo2, hB);
        hC = fmaf(xC.z, wo2, hC);  hD = fmaf(xD.z, wo2, hD);
        hA = fmaf(xA.w, wo3, hA);  hB = fmaf(xB.w, wo3, hB);
        hC = fmaf(xC.w, wo3, hC);  hD = fmaf(xD.w, wo3, hD);

        hA = fmaxf(hA, 0.0f);  hB = fmaxf(hB, 0.0f);
        hC = fmaxf(hC, 0.0f);  hD = fmaxf(hD, 0.0f);

        m = fmaxf(m, hA);
        if (v1) m = fmaxf(m, hB);
        if (v2) m = fmaxf(m, hC);
        if (v3) m = fmaxf(m, hD);

        if (n0 == c)       g_x2[j] = hA;
        if (v1 && n1 == c) g_x2[j] = hB;
        if (v2 && n2 == c) g_x2[j] = hC;
        if (v3 && n3 == c) g_x2[j] = hD;
    }
    atomicMax(&g_x1[j], __float_as_uint(m));
}

// ---------------------------------------------------------------------------
// Kernel 3a: head1 — k-split partial matvec.  W1 rows PRELOADED into regs
// before pdl_wait (independent of node); after wait only gk is read.
// Thread j (<188): one atomicAdd partial into g_g1[j].
// ---------------------------------------------------------------------------
__global__ void __launch_bounds__(192) head1_kernel(const float* __restrict__ W1) {
    __shared__ float gk[H1_ROWS];
    int t = threadIdx.x;
    int k0 = blockIdx.x * H1_ROWS;

    // preload this thread's 20 W1 values (input — independent of node)
    float wreg[H1_ROWS];
    if (t < L1_DIM) {
        const float* w = W1 + (size_t)k0 * L1_DIM + t;
        #pragma unroll
        for (int r = 0; r < H1_ROWS; r++)
            wreg[r] = __ldg(w + r * L1_DIM);
    }

    pdl_launch_dependents();           // head2 may preload W4/b1
    pdl_wait();                        // node's g_x1/g_x2 now complete

    if (t < H1_ROWS) {
        int k = k0 + t;
        gk[t] = (k < H_DIM) ? (g_x2[k] - __uint_as_float(g_x1[k]))
                            : g_md[k - H_DIM];
    }
    __syncthreads();

    if (t < L1_DIM) {
        float acc = 0.0f;
        #pragma unroll
        for (int r = 0; r < H1_ROWS; r++)
            acc = fmaf(gk[r], wreg[r], acc);
        atomicAdd(&g_g1[t], acc);
    }
}

// ---------------------------------------------------------------------------
// Kernel 3b: head2 — g1 = relu(g_g1 + b1); out = g1 @ W4 + b4.
// W4/b1/b4 preloaded before pdl_wait.  Resets g_g1 (replay invariant).
// ---------------------------------------------------------------------------
__global__ void __launch_bounds__(192) head2_kernel(const float* __restrict__ b1,
                                                    const float* __restrict__ W4,
                                                    const float* __restrict__ b4,
                                                    float* __restrict__ out) {
    __shared__ float g1s[L1_DIM];
    int t = threadIdx.x;
    int o    = t >> 5;                            // 0..4 (t<160)
    int lane = t & 31;

    // preload (inputs — independent of head1)
    float b1t = (t < L1_DIM) ? b1[t] : 0.0f;
    float wv[6];
    float b4o = 0.0f;
    if (t < 160) {
        #pragma unroll
        for (int q = 0; q < 6; q++) {
            int k = lane + q * 32;
            wv[q] = (k < L1_DIM) ? __ldg(&W4[k * 5 + o]) : 0.0f;
        }
        b4o = b4[o];
    }

    pdl_wait();                        // head1's g_g1 now complete

    if (t < L1_DIM) {
        g1s[t] = fmaxf(g_g1[t] + b1t, 0.0f);
        g_g1[t] = 0.0f;                          // restore replay invariant
    }
    __syncthreads();

    if (t < 160) {
        float s = 0.0f;
        #pragma unroll
        for (int q = 0; q < 6; q++) {
            int k = lane + q * 32;
            if (k < L1_DIM) s = fmaf(g1s[k], wv[q], s);
        }
        #pragma unroll
        for (int off = 16; off > 0; off >>= 1)
            s += __shfl_down_sync(0xffffffff, s, off);
        if (lane == 0) out[o] = s + b4o;
    }
}

// ---------------------------------------------------------------------------
// launch: prep -> edge -> node -> head1 -> head2, with programmatic stream
// serialization on every dependent launch (prologue overlap).
// ---------------------------------------------------------------------------
template <typename... Args>
static void launch_pdl(void (*kern)(Args...), dim3 grid, dim3 block,
                       Args... args) {
    cudaLaunchConfig_t cfg = {};
    cfg.gridDim = grid;
    cfg.blockDim = block;
    cfg.dynamicSmemBytes = 0;
    cfg.stream = 0;
    cudaLaunchAttribute attr[1];
    attr[0].id = cudaLaunchAttributeProgrammaticStreamSerialization;
    attr[0].val.programmaticStreamSerializationAllowed = 1;
    cfg.attrs = attr;
    cfg.numAttrs = 1;
    cudaLaunchKernelEx(&cfg, kern, args...);
}

extern "C" void kernel_launch(void* const* d_in, const int* in_sizes, int n_in,
                              void* d_out, int out_size) {
    const float* nf     = (const float*)d_in[0];
    const int*   ei     = (const int*)  d_in[1];
    const float* ew     = (const float*)d_in[2];
    const int*   center = (const int*)  d_in[3];
    const float* Wrel   = (const float*)d_in[4];
    const float* brel   = (const float*)d_in[5];
    const float* Wroot  = (const float*)d_in[6];
    const float* W2     = (const float*)d_in[7];
    const float* b2     = (const float*)d_in[8];
    const float* W21    = (const float*)d_in[9];
    const float* b21    = (const float*)d_in[10];
    const float* W1     = (const float*)d_in[11];
    const float* b1     = (const float*)d_in[12];
    const float* W4     = (const float*)d_in[13];
    const float* b4     = (const float*)d_in[14];
    float* out = (float*)d_out;

    int N = in_sizes[0] / 6;
    int E = in_sizes[2];

    prep_kernel<<<(N + 255) / 256, 256>>>(nf, N, center, W2, b2, W21, b21);
    int nvec = E >> 2;
    launch_pdl(edge_kernel, dim3((nvec + 255) / 256), dim3(256), ei, ew, E);
    launch_pdl(node_kernel, dim3(1024), dim3(192),
               Wrel, brel, Wroot, N, center, W1, W4);
    launch_pdl(head1_kernel, dim3(H1_BLOCKS), dim3(192), W1);
    launch_pdl(head2_kernel, dim3(1), dim3(192), b1, W4, b4, out);
}

// round 15
// speedup vs baseline: 1.0405x; 1.0405x over previous
#include <cuda_runtime.h>
#include <cstdint>

#define NMAX 200000
#define H_DIM 184
#define L1_DIM 188
#define GV_DIM (H_DIM + 16)   // 200 = k-dim of W1
#define H1_BLOCKS 10
#define H1_ROWS 20            // 10*20 = 200 = GV_DIM

// Per-node accumulator: agg (4f) + deg + pad => one 32B sector, both REDs of
// an edge hit a single L2 line.
struct __align__(32) NodeAcc {
    float4 agg;
    float  deg;
    float  pad0, pad1, pad2;
};

__device__ NodeAcc      g_nd[NMAX];
__device__ float4       g_x4[NMAX];       // packed node_feat[:, :4]
__device__ unsigned int g_x1[H_DIM];      // column max of h (uint bits; h>=0)
__device__ float        g_x2[H_DIM];      // h[center]
__device__ float        g_md[16];         // md MLP output (nf-only dependency)
// REPLAY INVARIANT: g_g1 == 0 at launch entry.  First call: BSS zero.
// Every call: head2 resets it after its final read (stream-serialized).
__device__ float        g_g1[L1_DIM];

__device__ __forceinline__ float rcp_fast(float x) {
    float r;
    asm("rcp.approx.f32 %0, %1;" : "=f"(r) : "f"(x));
    return r;
}

// ---------------------------------------------------------------------------
// Kernel 0: ONE pass per node: zero g_nd[i] (2 float4) + pack node_feat[:,:4]
// into g_x4[i].  md MLP on block 0 warp 0.  x1 zeroed by first H_DIM threads.
// ---------------------------------------------------------------------------
__global__ void __launch_bounds__(256) prep_kernel(
        const float* __restrict__ nf, int n_nodes,
        const int*   __restrict__ center,
        const float* __restrict__ W2,  const float* __restrict__ b2,
        const float* __restrict__ W21, const float* __restrict__ b21) {
    int stride = gridDim.x * blockDim.x;
    int tid = blockIdx.x * blockDim.x + threadIdx.x;

    // md = relu(relu(nf[c,4:6]@W2+b2)@W21+b21)  (block 0, warp 0)
    if (blockIdx.x == 0 && threadIdx.x < 32) {
        int t = threadIdx.x;
        int c = *center;
        float m0 = nf[(size_t)c * 6 + 4];
        float m1 = nf[(size_t)c * 6 + 5];
        float md1 = 0.0f;
        if (t < 16)
            md1 = fmaxf(fmaf(m0, W2[t], fmaf(m1, W2[16 + t], b2[t])), 0.0f);
        float s = (t < 16) ? b21[t] : 0.0f;
        #pragma unroll
        for (int k = 0; k < 16; k++) {
            float v = __shfl_sync(0xffffffff, md1, k);
            if (t < 16) s = fmaf(v, W21[k * 16 + t], s);
        }
        if (t < 16) g_md[t] = fmaxf(s, 0.0f);
    }

    if (tid < H_DIM) g_x1[tid] = 0u;

    const float4 z = make_float4(0.f, 0.f, 0.f, 0.f);
    for (int i = tid; i < n_nodes; i += stride) {
        const float2* p = reinterpret_cast<const float2*>(nf + (size_t)i * 6);
        float2 a = __ldg(p);
        float2 b = __ldg(p + 1);
        g_x4[i] = make_float4(a.x, a.y, b.x, b.y);
        float4* nd = reinterpret_cast<float4*>(&g_nd[i]);
        nd[0] = z;
        nd[1] = z;
    }
}

// ---------------------------------------------------------------------------
// Kernel 1: edge scatter.  One LDG.128 gather + red.v4 + red.f32, both REDs
// landing in the same 32B sector of g_nd[d].  (At the LTS-RMW floor.)
// ---------------------------------------------------------------------------
__device__ __forceinline__ void do_edge(int s, int d, float w) {
    float4 x = __ldg(&g_x4[s]);
    float* ap = reinterpret_cast<float*>(&g_nd[d]);
    asm volatile("red.global.add.v4.f32 [%0], {%1, %2, %3, %4};"
                 :: "l"(ap), "f"(x.x * w), "f"(x.y * w),
                    "f"(x.z * w), "f"(x.w * w)
                 : "memory");
    asm volatile("red.global.add.f32 [%0], %1;"
                 :: "l"(ap + 4), "f"(1.0f) : "memory");
}

__global__ void __launch_bounds__(256) edge_kernel(const int*   __restrict__ ei,
                                                   const float* __restrict__ ew, int E) {
    int i    = blockIdx.x * blockDim.x + threadIdx.x;
    int nvec = E >> 2;
    if (i < nvec) {
        int4   s = __ldcs(reinterpret_cast<const int4*>(ei) + i);
        int4   d = __ldcs(reinterpret_cast<const int4*>(ei + E) + i);
        float4 w = __ldcs(reinterpret_cast<const float4*>(ew) + i);
        do_edge(s.x, d.x, w.x);
        do_edge(s.y, d.y, w.y);
        do_edge(s.z, d.z, w.z);
        do_edge(s.w, d.w, w.w);
    }
    if (i == 0) {                                // tail (E % 4)
        for (int e = nvec * 4; e < E; e++)
            do_edge(ei[e], ei[E + e], ew[e]);
    }
}

// ---------------------------------------------------------------------------
// Kernel 2: h = relu(mean@W_rel + b_rel + x@W_root); 4 nodes per iteration.
// REGROUPED math: s1 = agg.wr (4 FMA), hx = b + x.wo (4 FMA),
// h = fma(s1, inv, hx) (1 FMA) — 9 FMA-pipe ops/(node,col) vs 12.
// Per-block running max, one atomicMax per column.  W1/W4 L2 prefetch.
// ---------------------------------------------------------------------------
__global__ void __launch_bounds__(192) node_kernel(
        const float* __restrict__ Wrel,
        const float* __restrict__ brel,
        const float* __restrict__ Wroot,
        int N, const int* __restrict__ center,
        const float* __restrict__ W1, const float* __restrict__ W4) {
    // L2 prefetch of head weights (2 lines per block, fire-and-forget)
    {
        const int W1_LINES = (GV_DIM * L1_DIM * 4 + 127) / 128;   // 1175
        int l = blockIdx.x + (int)gridDim.x * (threadIdx.x & 1);
        if (threadIdx.x < 2 && l < W1_LINES) {
            const char* p = reinterpret_cast<const char*>(W1) + (size_t)l * 128;
            asm volatile("prefetch.global.L2 [%0];" :: "l"(p));
        }
        if (blockIdx.x == 0 && threadIdx.x >= 64 && threadIdx.x < 94) {
            const char* p = reinterpret_cast<const char*>(W4)
                          + (size_t)(threadIdx.x - 64) * 128;
            asm volatile("prefetch.global.L2 [%0];" :: "l"(p));
        }
    }

    int j = threadIdx.x;
    if (j >= H_DIM) return;

    float wr0 = Wrel[j],             wr1 = Wrel[H_DIM + j];
    float wr2 = Wrel[2 * H_DIM + j], wr3 = Wrel[3 * H_DIM + j];
    float wo0 = Wroot[j],            wo1 = Wroot[H_DIM + j];
    float wo2 = Wroot[2 * H_DIM + j], wo3 = Wroot[3 * H_DIM + j];
    float bj  = brel[j];
    int   c   = *center;

    int Q = (N + 3) >> 2;
    float m = 0.0f;                              // h >= 0 after ReLU

    for (int n0 = blockIdx.x; n0 < Q; n0 += gridDim.x) {
        int n1 = n0 + Q, n2 = n0 + 2 * Q, n3 = n0 + 3 * Q;
        bool v1 = (n1 < N), v2 = (n2 < N), v3 = (n3 < N);
        int c1 = v1 ? n1 : n0, c2 = v2 ? n2 : n0, c3 = v3 ? n3 : n0;

        float4 agA = g_nd[n0].agg;  float dgA = g_nd[n0].deg;  float4 xA = g_x4[n0];
        float4 agB = g_nd[c1].agg;  float dgB = g_nd[c1].deg;  float4 xB = g_x4[c1];
        float4 agC = g_nd[c2].agg;  float dgC = g_nd[c2].deg;  float4 xC = g_x4[c2];
        float4 agD = g_nd[c3].agg;  float dgD = g_nd[c3].deg;  float4 xD = g_x4[c3];

        float iA = rcp_fast(fmaxf(dgA, 1.0f));
        float iB = rcp_fast(fmaxf(dgB, 1.0f));
        float iC = rcp_fast(fmaxf(dgC, 1.0f));
        float iD = rcp_fast(fmaxf(dgD, 1.0f));

        // s = agg . wr   (4 FMA-pipe ops each)
        float sA = agA.x * wr0, sB = agB.x * wr0;
        float sC = agC.x * wr0, sD = agD.x * wr0;
        sA = fmaf(agA.y, wr1, sA);  sB = fmaf(agB.y, wr1, sB);
        sC = fmaf(agC.y, wr1, sC);  sD = fmaf(agD.y, wr1, sD);
        sA = fmaf(agA.z, wr2, sA);  sB = fmaf(agB.z, wr2, sB);
        sC = fmaf(agC.z, wr2, sC);  sD = fmaf(agD.z, wr2, sD);
        sA = fmaf(agA.w, wr3, sA);  sB = fmaf(agB.w, wr3, sB);
        sC = fmaf(agC.w, wr3, sC);  sD = fmaf(agD.w, wr3, sD);

        // hx = b + x . wo  (4 FMA each)
        float hA = fmaf(xA.x, wo0, bj),  hB = fmaf(xB.x, wo0, bj);
        float hC = fmaf(xC.x, wo0, bj),  hD = fmaf(xD.x, wo0, bj);
        hA = fmaf(xA.y, wo1, hA);  hB = fmaf(xB.y, wo1, hB);
        hC = fmaf(xC.y, wo1, hC);  hD = fmaf(xD.y, wo1, hD);
        hA = fmaf(xA.z, wo2, hA);  hB = fmaf(xB.z, wo2, hB);
        hC = fmaf(xC.z, wo2, hC);  hD = fmaf(xD.z, wo2, hD);
        hA = fmaf(xA.w, wo3, hA);  hB = fmaf(xB.w, wo3, hB);
        hC = fmaf(xC.w, wo3, hC);  hD = fmaf(xD.w, wo3, hD);

        // h = s * inv + hx  (1 FMA each)
        hA = fmaf(sA, iA, hA);  hB = fmaf(sB, iB, hB);
        hC = fmaf(sC, iC, hC);  hD = fmaf(sD, iD, hD);

        hA = fmaxf(hA, 0.0f);  hB = fmaxf(hB, 0.0f);
        hC = fmaxf(hC, 0.0f);  hD = fmaxf(hD, 0.0f);

        m = fmaxf(m, hA);
        if (v1) m = fmaxf(m, hB);
        if (v2) m = fmaxf(m, hC);
        if (v3) m = fmaxf(m, hD);

        if (n0 == c)       g_x2[j] = hA;
        if (v1 && n1 == c) g_x2[j] = hB;
        if (v2 && n2 == c) g_x2[j] = hC;
        if (v3 && n3 == c) g_x2[j] = hD;
    }
    atomicMax(&g_x1[j], __float_as_uint(m));
}

// ---------------------------------------------------------------------------
// Kernel 3a: head1 — k-split partial matvec.  Block b owns W1 rows
// [b*20, b*20+20); rows contiguous => coalesced.  One atomicAdd per thread.
// ---------------------------------------------------------------------------
__global__ void __launch_bounds__(192) head1_kernel(const float* __restrict__ W1) {
    __shared__ float gk[H1_ROWS];
    int t = threadIdx.x;
    int k0 = blockIdx.x * H1_ROWS;

    if (t < H1_ROWS) {
        int k = k0 + t;
        gk[t] = (k < H_DIM) ? (g_x2[k] - __uint_as_float(g_x1[k]))
                            : g_md[k - H_DIM];
    }
    __syncthreads();

    if (t < L1_DIM) {
        float acc = 0.0f;
        const float* w = W1 + (size_t)k0 * L1_DIM + t;
        #pragma unroll
        for (int r = 0; r < H1_ROWS; r++)
            acc = fmaf(gk[r], __ldg(w + r * L1_DIM), acc);
        atomicAdd(&g_g1[t], acc);
    }
}

// ---------------------------------------------------------------------------
// Kernel 3b: head2 — g1 = relu(g_g1 + b1); out = g1 @ W4 + b4.
// Resets g_g1 to zero after reading (replay invariant).
// ---------------------------------------------------------------------------
__global__ void __launch_bounds__(192) head2_kernel(const float* __restrict__ b1,
                                                    const float* __restrict__ W4,
                                                    const float* __restrict__ b4,
                                                    float* __restrict__ out) {
    __shared__ float g1s[L1_DIM];
    int t = threadIdx.x;
    if (t < L1_DIM) {
        g1s[t] = fmaxf(g_g1[t] + b1[t], 0.0f);
        g_g1[t] = 0.0f;                          // restore replay invariant
    }
    __syncthreads();

    if (t < 160) {
        int o    = t >> 5;                        // 0..4
        int lane = t & 31;
        float s = 0.0f;
        for (int k = lane; k < L1_DIM; k += 32)
            s = fmaf(g1s[k], __ldg(&W4[k * 5 + o]), s);
        #pragma unroll
        for (int off = 16; off > 0; off >>= 1)
            s += __shfl_down_sync(0xffffffff, s, off);
        if (lane == 0) out[o] = s + b4[o];
    }
}

// ---------------------------------------------------------------------------
extern "C" void kernel_launch(void* const* d_in, const int* in_sizes, int n_in,
                              void* d_out, int out_size) {
    const float* nf     = (const float*)d_in[0];
    const int*   ei     = (const int*)  d_in[1];
    const float* ew     = (const float*)d_in[2];
    const int*   center = (const int*)  d_in[3];
    const float* Wrel   = (const float*)d_in[4];
    const float* brel   = (const float*)d_in[5];
    const float* Wroot  = (const float*)d_in[6];
    const float* W2     = (const float*)d_in[7];
    const float* b2     = (const float*)d_in[8];
    const float* W21    = (const float*)d_in[9];
    const float* b21    = (const float*)d_in[10];
    const float* W1     = (const float*)d_in[11];
    const float* b1     = (const float*)d_in[12];
    const float* W4     = (const float*)d_in[13];
    const float* b4     = (const float*)d_in[14];
    float* out = (float*)d_out;

    int N = in_sizes[0] / 6;
    int E = in_sizes[2];

    prep_kernel<<<(N + 255) / 256, 256>>>(nf, N, center, W2, b2, W21, b21);
    int nvec = E >> 2;
    edge_kernel<<<(nvec + 255) / 256, 256>>>(ei, ew, E);
    node_kernel<<<1024, 192>>>(Wrel, brel, Wroot, N, center, W1, W4);
    head1_kernel<<<H1_BLOCKS, 192>>>(W1);
    head2_kernel<<<1, 192>>>(b1, W4, b4, out);
}